// round 11
// baseline (speedup 1.0000x reference)
#include <cuda_runtime.h>
#include <cuda_bf16.h>
#include <math.h>
#include <stdint.h>

#define BB 2048
#define TT 80
#define LL 128
#define MT 16             // batch rows per CTA
#define NCF 128           // grid
#define SVS 136           // padded V row stride in bf16 elems

// ---- helpers ----
__device__ __forceinline__ uint32_t packbf2(float lo, float hi) {
    uint32_t r;
    asm("cvt.rn.satfinite.bf16x2.f32 %0, %1, %2;" : "=r"(r) : "f"(hi), "f"(lo));
    return r;
}
__device__ __forceinline__ uint32_t smem_u32(const void* p) {
    uint32_t a;
    asm("{ .reg .u64 t; cvta.to.shared.u64 t, %1; cvt.u32.u64 %0, t; }" : "=r"(a) : "l"(p));
    return a;
}
__device__ __forceinline__ void ldsm4(uint32_t r[4], uint32_t addr) {
    asm volatile("ldmatrix.sync.aligned.m8n8.x4.shared.b16 {%0,%1,%2,%3}, [%4];"
        : "=r"(r[0]), "=r"(r[1]), "=r"(r[2]), "=r"(r[3]) : "r"(addr));
}
__device__ __forceinline__ void mma16816(float d[4], const uint32_t a[4], const uint32_t b[2]) {
    asm volatile("mma.sync.aligned.m16n8k16.row.col.f32.bf16.bf16.f32 "
        "{%0,%1,%2,%3}, {%4,%5,%6,%7}, {%8,%9}, {%0,%1,%2,%3};"
        : "+f"(d[0]), "+f"(d[1]), "+f"(d[2]), "+f"(d[3])
        : "r"(a[0]), "r"(a[1]), "r"(a[2]), "r"(a[3]), "r"(b[0]), "r"(b[1]));
}

// -------------------------------------------------------------------------
// Fused CRF kernel. 128 CTAs x 256 thr (8 warps), 1 CTA/SM, MT=16 rows.
// Warp w owns n-slice [16w,16w+16). B = exp(trans) in regs.
// Fragment identity: warp's D packs ARE the A-frag of k-tile w next step
// (one ldsm saved; 2 MMAs start with zero LDS wait).
// Renorm: V stored UNSCALED; per-warp row-max written before the regular
// top sync; 1/m applied to next step's D (no extra __syncthreads).
// Emissions: LDG 2 steps ahead; exp + prefetch hidden after the V store.
// -------------------------------------------------------------------------
__global__ void __launch_bounds__(256, 1) crf_fwd_kernel(
    const float* __restrict__ x,
    const float* __restrict__ trans,
    const float* __restrict__ st,
    const float* __restrict__ et,
    const int*   __restrict__ y,
    float*       __restrict__ out)
{
    __shared__ __align__(16) __nv_bfloat16 sV[2][MT * SVS];
    __shared__ float sSt[LL];
    __shared__ float sRed[8][MT];
    __shared__ float sS[MT];
    __shared__ float sNum[MT][16];

    const int tid  = threadIdx.x;
    const int w    = tid >> 5;
    const int lane = tid & 31;
    const int gb   = blockIdx.x * MT;

    // ---- static B fragments: exp(trans)[k][n] in mma col-B layout ----
    uint32_t Bf[8][2][2];
    {
        const int jn = 16 * w + (lane >> 2);
        const int kb = (lane & 3) * 2;
        #pragma unroll
        for (int ks = 0; ks < 8; ks++)
            #pragma unroll
            for (int nt = 0; nt < 2; nt++) {
                int j  = jn + nt * 8;
                int k0 = ks * 16 + kb;
                Bf[ks][nt][0] = packbf2(__expf(trans[k0 * LL + j]),
                                        __expf(trans[(k0 + 1) * LL + j]));
                Bf[ks][nt][1] = packbf2(__expf(trans[(k0 + 8) * LL + j]),
                                        __expf(trans[(k0 + 9) * LL + j]));
            }
    }
    const int rQ  = lane >> 2;
    const int cQ2 = (lane & 3) * 2;
    const int c0  = 16 * w + cQ2;
    float eet[2][2];
    eet[0][0] = __expf(et[c0]);     eet[0][1] = __expf(et[c0 + 1]);
    eet[1][0] = __expf(et[c0 + 8]); eet[1][1] = __expf(et[c0 + 9]);
    if (tid < LL) sSt[tid] = st[tid];
    if (tid < MT) sS[tid] = 0.0f;

    // ---- gold-path numerator: 16 threads per row, 5 chunks each ----
    {
        const int nrow = tid >> 4, nsub = tid & 15;
        const int*   yr = y + (gb + nrow) * TT;
        const float* xn = x + (size_t)(gb + nrow) * TT * LL;
        float nacc = 0.0f;
        #pragma unroll
        for (int k = 0; k < 5; k++) {
            int t = nsub + 16 * k;
            int cur = yr[t];
            nacc += xn[t * LL + cur];
            if (t < TT - 1) nacc += trans[cur * LL + yr[t + 1]];
        }
        if (nsub == 0)  nacc += st[yr[0]];
        if (nsub == 15) nacc += et[yr[TT - 1]];
        sNum[nrow][nsub] = nacc;
    }
    __syncthreads();

    // ---- t = 0 init: V0 = exp(st + x0), 16 thr/row x 8 cols ----
    {
        const int prow = tid >> 4;
        const int pc   = (tid & 15) * 8;
        const float* xr = x + ((size_t)(gb + prow) * TT) * LL + pc;
        float4 a = *(const float4*)(xr);
        float4 b = *(const float4*)(xr + 4);
        uint4 v;
        v.x = packbf2(__expf(sSt[pc + 0] + a.x), __expf(sSt[pc + 1] + a.y));
        v.y = packbf2(__expf(sSt[pc + 2] + a.z), __expf(sSt[pc + 3] + a.w));
        v.z = packbf2(__expf(sSt[pc + 4] + b.x), __expf(sSt[pc + 5] + b.y));
        v.w = packbf2(__expf(sSt[pc + 6] + b.z), __expf(sSt[pc + 7] + b.w));
        *(uint4*)&sV[0][prow * SVS + pc] = v;
    }

    // ---- emission pipeline: Pcur = exp(x_t); xrn = x(t+1); xrn2 = x(t+2) ----
    const float* xrA = x + ((size_t)(gb + rQ)     * TT) * LL + c0;
    const float* xrB = x + ((size_t)(gb + rQ + 8) * TT) * LL + c0;
    float2 xrn[4], xrn2[4];          // [h*2+nt]
    #pragma unroll
    for (int nt = 0; nt < 2; nt++) {
        xrn[0 + nt]  = *(const float2*)(xrA + LL + nt * 8);
        xrn[2 + nt]  = *(const float2*)(xrB + LL + nt * 8);
        xrn2[0 + nt] = *(const float2*)(xrA + 2 * LL + nt * 8);
        xrn2[2 + nt] = *(const float2*)(xrB + 2 * LL + nt * 8);
    }
    float Pcur[2][4];                // [nt][2h+j]
    #pragma unroll
    for (int h = 0; h < 2; h++)
        #pragma unroll
        for (int nt = 0; nt < 2; nt++) {
            Pcur[nt][2 * h]     = __expf(xrn[h * 2 + nt].x);
            Pcur[nt][2 * h + 1] = __expf(xrn[h * 2 + nt].y);
        }
    #pragma unroll
    for (int q = 0; q < 4; q++) { xrn[q] = xrn2[q]; }
    #pragma unroll
    for (int nt = 0; nt < 2; nt++) {
        xrn2[0 + nt] = *(const float2*)(xrA + 3 * LL + nt * 8);
        xrn2[2 + nt] = *(const float2*)(xrB + 3 * LL + nt * 8);
    }

    // ---- per-lane ldmatrix / STS offsets (bytes) ----
    const int rowL = lane & 15;
    const int sel8 = (lane >> 4) * 8;
    const uint32_t Aoff = (rowL * SVS + sel8) * 2;
    uint32_t Voff[2];
    #pragma unroll
    for (int h = 0; h < 2; h++)
        Voff[h] = ((h * 8 + rQ) * SVS + 16 * w + cQ2) * 2;

    const uint32_t svb[2] = { smem_u32(&sV[0][0]), smem_u32(&sV[1][0]) };

    float val[2][4];
    uint32_t Afw[4];                 // own k-tile A-frag (valid from t>=2)

    for (int t = 1; t < TT; t++) {
        const int rd = (t - 1) & 1, wr = t & 1;
        __syncthreads();

        // A fragments: 7 via ldsm, own via fragment identity
        uint32_t Af[8][4];
        #pragma unroll
        for (int ks = 0; ks < 8; ks++)
            if (ks != w) ldsm4(Af[ks], svb[rd] + Aoff + ks * 32);
        if (t == 1) {
            ldsm4(Af[w], svb[rd] + Aoff + w * 32);
        } else {
            Af[w][0] = Afw[0]; Af[w][1] = Afw[1];
            Af[w][2] = Afw[2]; Af[w][3] = Afw[3];
        }

        // deferred renorm apply (overlaps ldsm latency)
        float inv0 = 1.0f, inv1 = 1.0f;
        if (((t - 1) & 7) == 0 && t > 1) {
            float m0 = sRed[0][rQ], m1 = sRed[0][rQ + 8];
            #pragma unroll
            for (int w2 = 1; w2 < 8; w2++) {
                m0 = fmaxf(m0, sRed[w2][rQ]);
                m1 = fmaxf(m1, sRed[w2][rQ + 8]);
            }
            inv0 = __fdividef(1.0f, m0);
            inv1 = __fdividef(1.0f, m1);
            if (w == 0 && (lane & 3) == 0) {
                sS[rQ]     += __logf(m0);
                sS[rQ + 8] += __logf(m1);
            }
        }

        // split-K GEMM
        float D0[2][4] = {{0.f,0.f,0.f,0.f},{0.f,0.f,0.f,0.f}};
        float D1[2][4] = {{0.f,0.f,0.f,0.f},{0.f,0.f,0.f,0.f}};
        #pragma unroll
        for (int ks = 0; ks < 4; ks++) {
            mma16816(D0[0], Af[ks],     Bf[ks][0]);
            mma16816(D0[1], Af[ks],     Bf[ks][1]);
            mma16816(D1[0], Af[ks + 4], Bf[ks + 4][0]);
            mma16816(D1[1], Af[ks + 4], Bf[ks + 4][1]);
        }
        #pragma unroll
        for (int nt = 0; nt < 2; nt++) {
            val[nt][0] = (D0[nt][0] + D1[nt][0]) * Pcur[nt][0] * inv0;
            val[nt][1] = (D0[nt][1] + D1[nt][1]) * Pcur[nt][1] * inv0;
            val[nt][2] = (D0[nt][2] + D1[nt][2]) * Pcur[nt][2] * inv1;
            val[nt][3] = (D0[nt][3] + D1[nt][3]) * Pcur[nt][3] * inv1;
        }

        // renorm collect every 8 steps (no extra sync; applied next step)
        if ((t & 7) == 0) {
            float m0 = fmaxf(fmaxf(val[0][0], val[0][1]), fmaxf(val[1][0], val[1][1]));
            float m1 = fmaxf(fmaxf(val[0][2], val[0][3]), fmaxf(val[1][2], val[1][3]));
            m0 = fmaxf(m0, __shfl_xor_sync(0xffffffffu, m0, 1));
            m0 = fmaxf(m0, __shfl_xor_sync(0xffffffffu, m0, 2));
            m1 = fmaxf(m1, __shfl_xor_sync(0xffffffffu, m1, 1));
            m1 = fmaxf(m1, __shfl_xor_sync(0xffffffffu, m1, 2));
            if ((lane & 3) == 0) {
                sRed[w][rQ]     = m0;
                sRed[w][rQ + 8] = m1;
            }
        }

        // pack: these regs are BOTH the STS payload and next step's own A-frag
        Afw[0] = packbf2(val[0][0], val[0][1]);
        Afw[1] = packbf2(val[0][2], val[0][3]);
        Afw[2] = packbf2(val[1][0], val[1][1]);
        Afw[3] = packbf2(val[1][2], val[1][3]);

        if (t < TT - 1) {
            char* vb = (char*)&sV[wr][0];
            *(uint32_t*)(vb + Voff[0])      = Afw[0];
            *(uint32_t*)(vb + Voff[1])      = Afw[1];
            *(uint32_t*)(vb + Voff[0] + 16) = Afw[2];
            *(uint32_t*)(vb + Voff[1] + 16) = Afw[3];

            // hidden work before next barrier: exp for t+1, prefetch t+3
            #pragma unroll
            for (int h = 0; h < 2; h++)
                #pragma unroll
                for (int nt = 0; nt < 2; nt++) {
                    Pcur[nt][2 * h]     = __expf(xrn[h * 2 + nt].x);
                    Pcur[nt][2 * h + 1] = __expf(xrn[h * 2 + nt].y);
                }
            #pragma unroll
            for (int q = 0; q < 4; q++) xrn[q] = xrn2[q];
            if (t + 3 < TT) {
                #pragma unroll
                for (int nt = 0; nt < 2; nt++) {
                    xrn2[0 + nt] = *(const float2*)(xrA + (size_t)(t + 3) * LL + nt * 8);
                    xrn2[2 + nt] = *(const float2*)(xrB + (size_t)(t + 3) * LL + nt * 8);
                }
            }
        }
    }

    // ---- epilogue: Z per row ----
    #pragma unroll
    for (int h = 0; h < 2; h++) {
        float z = val[0][2*h] * eet[0][0] + val[0][2*h+1] * eet[0][1]
                + val[1][2*h] * eet[1][0] + val[1][2*h+1] * eet[1][1];
        z += __shfl_xor_sync(0xffffffffu, z, 1);
        z += __shfl_xor_sync(0xffffffffu, z, 2);
        if ((lane & 3) == 0) sRed[w][h * 8 + rQ] = z;
    }
    __syncthreads();
    if (tid < MT) {
        float Z = 0.0f;
        #pragma unroll
        for (int w2 = 0; w2 < 8; w2++) Z += sRed[w2][tid];
        float num = 0.0f;
        #pragma unroll
        for (int k = 0; k < 16; k++) num += sNum[tid][k];
        out[gb + tid] = num - (sS[tid] + __logf(Z));
    }
}

// -------------------------------------------------------------------------
extern "C" void kernel_launch(void* const* d_in, const int* in_sizes, int n_in,
                              void* d_out, int out_size)
{
    const float* x     = (const float*)d_in[0];
    const float* trans = (const float*)d_in[1];
    const float* st    = (const float*)d_in[2];
    const float* et    = (const float*)d_in[3];
    const int*   y     = (const int*)  d_in[4];
    float*       out   = (float*)d_out;

    crf_fwd_kernel<<<NCF, 256>>>(x, trans, st, et, y, out);
}